// round 1
// baseline (speedup 1.0000x reference)
#include <cuda_runtime.h>
#include <math.h>

// Problem constants
#define TT   256
#define BB   32
#define DD   512
#define HH   8
#define HDd  64
#define ETA  4
#define RR   4
#define FEAT 256   // HD*ETA
#define MM   (TT*BB)        // 8192 rows
#define NPROJ (5*HH*HDd)    // 2560
#define NP    (3*HH*ETA)    // 96

// Scratch (device globals; allocation-free per harness rules)
__device__ float g_proj[(size_t)MM * NPROJ];   // q,k,v,beta,gamma (pre-activation)
__device__ float g_p[(size_t)MM * NP];         // p1,p2,p3 (pre-activation)
__device__ float g_attn[(size_t)MM * DD];      // attn reshaped (T*B, H*HD)

// ---------------------------------------------------------------------------
// Generic GEMM: C[M x Ntot] = A[M x K] * B^T, where B rows are gathered from
// up to 5 weight matrices each with `nper` rows of length K (row-major).
// ---------------------------------------------------------------------------
struct WSet {
    const float* w[5];
    int nper;
};

#define BM 128
#define BN 128
#define BK 16

__global__ __launch_bounds__(256) void gemm_bt_kernel(
    const float* __restrict__ A, WSet ws, float* __restrict__ C,
    int M, int Ntot, int K, int ldc, const float* __restrict__ bias)
{
    __shared__ float As[BK][BM];
    __shared__ float Bs[BK][BN];

    const int tid = threadIdx.x;
    const int m0 = blockIdx.y * BM;
    const int n0 = blockIdx.x * BN;
    const int tx = tid & 15;       // 0..15 -> n micro
    const int ty = tid >> 4;       // 0..15 -> m micro

    float acc[8][8];
#pragma unroll
    for (int i = 0; i < 8; i++)
#pragma unroll
        for (int j = 0; j < 8; j++) acc[i][j] = 0.f;

    for (int k0 = 0; k0 < K; k0 += BK) {
        // Load A tile (128 x 16): 512 float4 total, 2 per thread
#pragma unroll
        for (int it = 0; it < 2; it++) {
            int idx = tid + it * 256;
            int row = idx >> 2;
            int cv  = (idx & 3) * 4;
            float4 a = *reinterpret_cast<const float4*>(
                &A[(size_t)(m0 + row) * K + k0 + cv]);
            As[cv + 0][row] = a.x;
            As[cv + 1][row] = a.y;
            As[cv + 2][row] = a.z;
            As[cv + 3][row] = a.w;
        }
        // Load B tile (128 x 16) gathered from WSet
#pragma unroll
        for (int it = 0; it < 2; it++) {
            int idx = tid + it * 256;
            int row = idx >> 2;
            int cv  = (idx & 3) * 4;
            int n = n0 + row;
            float4 bv = make_float4(0.f, 0.f, 0.f, 0.f);
            if (n < Ntot) {
                const float* wp = ws.w[n / ws.nper] + (size_t)(n % ws.nper) * K;
                bv = *reinterpret_cast<const float4*>(&wp[k0 + cv]);
            }
            Bs[cv + 0][row] = bv.x;
            Bs[cv + 1][row] = bv.y;
            Bs[cv + 2][row] = bv.z;
            Bs[cv + 3][row] = bv.w;
        }
        __syncthreads();

#pragma unroll
        for (int kk = 0; kk < BK; kk++) {
            float af[8], bf[8];
#pragma unroll
            for (int i = 0; i < 8; i++) af[i] = As[kk][ty * 8 + i];
#pragma unroll
            for (int j = 0; j < 8; j++) bf[j] = Bs[kk][tx * 8 + j];
#pragma unroll
            for (int i = 0; i < 8; i++)
#pragma unroll
                for (int j = 0; j < 8; j++)
                    acc[i][j] = fmaf(af[i], bf[j], acc[i][j]);
        }
        __syncthreads();
    }

#pragma unroll
    for (int i = 0; i < 8; i++) {
        int m = m0 + ty * 8 + i;
#pragma unroll
        for (int j = 0; j < 8; j++) {
            int n = n0 + tx * 8 + j;
            if (n < Ntot) {
                float v = acc[i][j];
                if (bias) v += bias[n];
                C[(size_t)m * ldc + n] = v;
            }
        }
    }
}

// ---------------------------------------------------------------------------
// Recurrence kernel: one block per (b,h); 256 threads = one per FEAT element.
// thread tid: e = tid>>6 (eta index / also r index for v-state), d = tid&63.
// ---------------------------------------------------------------------------
__device__ __forceinline__ float sigf(float x) {
    return 1.f / (1.f + __expf(-x));
}

__global__ __launch_bounds__(256) void recur_kernel(
    const float* __restrict__ proj,   // [MM][2560]
    const float* __restrict__ pproj,  // [MM][96]
    const int*   __restrict__ term,   // [MM]
    const float* __restrict__ tkp,    // (B,R,H,FEAT)
    const float* __restrict__ tvp,    // (B,R,H,HD)
    const float* __restrict__ sprev,  // (B,H,FEAT)
    const float* __restrict__ tick,   // (B,)
    float* __restrict__ attn)         // [MM][512]
{
    const int bh = blockIdx.x;
    const int b = bh >> 3;
    const int h = bh & 7;
    const int tid = threadIdx.x;
    const int e = tid >> 6;   // eta idx AND r idx for v-state
    const int d = tid & 63;   // hd idx

    __shared__ float sq[64], sk[64], sv[64], sb[64], sg[64];
    __shared__ float sp1[4], sp2[4], sp3[4];
    __shared__ float red[5][8];
    __shared__ float fin[5];
    __shared__ float kvbuf[256];

    // Load initial states
    float ks0 = tkp[((size_t)(b * RR + 0) * HH + h) * FEAT + tid];
    float ks1 = tkp[((size_t)(b * RR + 1) * HH + h) * FEAT + tid];
    float ks2 = tkp[((size_t)(b * RR + 2) * HH + h) * FEAT + tid];
    float ks3 = tkp[((size_t)(b * RR + 3) * HH + h) * FEAT + tid];
    float vs  = tvp[((size_t)(b * RR + e) * HH + h) * HDd + d];
    float ss  = sprev[((size_t)(b * HH + h)) * FEAT + tid];

    const float PI = 3.14159265358979323846f;
    const float tk = tick[b];

    // Oscillator state: cr[r] = cos((t+1+tick)*omega_r), maintained by rotation.
    float cr0, cr1, cr2, cr3, sr0, sr1, sr2, sr3;
    float cw0, cw1, cw2, cw3, sw0, sw1, sw2, sw3;
    {
        float om0 = -PI;
        float om1 = -PI + 2.f * PI / 3.f;
        float om2 = -PI + 4.f * PI / 3.f;
        float om3 = PI;
        float a;
        a = (1.f + tk) * om0; cr0 = cosf(a); sr0 = sinf(a);
        a = (1.f + tk) * om1; cr1 = cosf(a); sr1 = sinf(a);
        a = (1.f + tk) * om2; cr2 = cosf(a); sr2 = sinf(a);
        a = (1.f + tk) * om3; cr3 = cosf(a); sr3 = sinf(a);
        cw0 = cosf(om0); sw0 = sinf(om0);
        cw1 = cosf(om1); sw1 = sinf(om1);
        cw2 = cosf(om2); sw2 = sinf(om2);
        cw3 = cosf(om3); sw3 = sinf(om3);
    }

    for (int t = 0; t < TT; t++) {
        const int m = t * BB + b;
        const float* pr = proj + (size_t)m * NPROJ + h * HDd;

        // Stage per-step operands into smem
        if (tid < 64) {
            sq[tid] = pr[tid];
        } else if (tid < 128) {
            sk[tid - 64] = pr[512 + (tid - 64)];
        } else if (tid < 192) {
            sv[tid - 128] = pr[1024 + (tid - 128)];
        } else {
            sb[tid - 192] = sigf(pr[1536 + (tid - 192)]);
        }
        if (tid >= 64 && tid < 128) {
            sg[tid - 64] = sigf(pr[2048 + (tid - 64)]);
        }
        const float* pp = pproj + (size_t)m * NP + h * ETA;
        if (tid < 4)       sp1[tid]     = pp[tid];
        else if (tid < 8)  sp2[tid - 4] = pp[32 + (tid - 4)];
        else if (tid < 12) sp3[tid - 8] = sigf(pp[64 + (tid - 8)]);

        const float tf = 1.f - (float)term[m];
        __syncthreads();   // S1

        // Per-feature compute
        const float qd = sq[d], kd = sk[d];
        const float phi = fmaxf(qd * sp2[e], 0.f);
        const float psi = fmaxf(kd * sp1[e], 0.f);
        const float gf  = sg[d] * sp3[e];
        const float gk  = psi * gf;
        const float dg  = (1.f - gf) * tf;

        ss = dg * ss + gk;
        float v4 = ss * phi;

        ks0 = dg * ks0 + gk * cr0;
        ks1 = dg * ks1 + gk * cr1;
        ks2 = dg * ks2 + gk * cr2;
        ks3 = dg * ks3 + gk * cr3;
        float v0 = ks0 * phi;
        float v1 = ks1 * phi;
        float v2 = ks2 * phi;
        float v3 = ks3 * phi;

        // V-state update (thread owns (r=e, d))
        float ce = (e == 0) ? cr0 : (e == 1) ? cr1 : (e == 2) ? cr2 : cr3;
        const float bd = sb[d];
        const float vv = sv[d];
        vs = (1.f - bd) * tf * vs + (vv * bd) * ce;

        // Block reduce: kdq[0..3], norm
#pragma unroll
        for (int o = 16; o > 0; o >>= 1) {
            v0 += __shfl_down_sync(0xffffffffu, v0, o);
            v1 += __shfl_down_sync(0xffffffffu, v1, o);
            v2 += __shfl_down_sync(0xffffffffu, v2, o);
            v3 += __shfl_down_sync(0xffffffffu, v3, o);
            v4 += __shfl_down_sync(0xffffffffu, v4, o);
        }
        const int warp = tid >> 5;
        if ((tid & 31) == 0) {
            red[0][warp] = v0;
            red[1][warp] = v1;
            red[2][warp] = v2;
            red[3][warp] = v3;
            red[4][warp] = v4;
        }
        __syncthreads();   // S2
        if (tid < 5) {
            float s = 0.f;
#pragma unroll
            for (int w = 0; w < 8; w++) s += red[tid][w];
            fin[tid] = s;
        }
        __syncthreads();   // S3

        const float kdq_e = fin[e];
        const float norm  = fin[4];
        kvbuf[tid] = vs * kdq_e;
        __syncthreads();   // S4

        if (tid < 64) {
            float kv = kvbuf[tid] + kvbuf[tid + 64] + kvbuf[tid + 128] + kvbuf[tid + 192];
            attn[(size_t)m * DD + h * HDd + tid] = kv / (8.f * norm + 1e-6f);
        }

        // Advance oscillator (post-use: step t uses angle (t+1+tick)*omega)
        float c2, s2;
        c2 = cr0 * cw0 - sr0 * sw0; s2 = sr0 * cw0 + cr0 * sw0; cr0 = c2; sr0 = s2;
        c2 = cr1 * cw1 - sr1 * sw1; s2 = sr1 * cw1 + cr1 * sw1; cr1 = c2; sr1 = s2;
        c2 = cr2 * cw2 - sr2 * sw2; s2 = sr2 * cw2 + cr2 * sw2; cr2 = c2; sr2 = s2;
        c2 = cr3 * cw3 - sr3 * sw3; s2 = sr3 * cw3 + cr3 * sw3; cr3 = c2; sr3 = s2;
    }
}

// ---------------------------------------------------------------------------
extern "C" void kernel_launch(void* const* d_in, const int* in_sizes, int n_in,
                              void* d_out, int out_size)
{
    const float* inputs = (const float*)d_in[0];
    const int*   term   = (const int*)d_in[1];
    const float* tkp    = (const float*)d_in[2];
    const float* tvp    = (const float*)d_in[3];
    const float* sprev  = (const float*)d_in[4];
    const float* tick   = (const float*)d_in[5];
    const float* Wq     = (const float*)d_in[6];
    const float* Wk     = (const float*)d_in[7];
    const float* Wv     = (const float*)d_in[8];
    const float* Wb     = (const float*)d_in[9];
    const float* Wg     = (const float*)d_in[10];
    const float* Wp1    = (const float*)d_in[11];
    const float* Wp2    = (const float*)d_in[12];
    const float* Wp3    = (const float*)d_in[13];
    const float* Wo     = (const float*)d_in[14];
    const float* bo     = (const float*)d_in[15];

    void* p;
    cudaGetSymbolAddress(&p, g_proj);
    float* proj = (float*)p;
    cudaGetSymbolAddress(&p, g_p);
    float* pp = (float*)p;
    cudaGetSymbolAddress(&p, g_attn);
    float* attn = (float*)p;

    // 1) Fused q,k,v,beta,gamma projection: (8192 x 2560) = X @ Wcat^T
    {
        WSet ws; ws.w[0] = Wq; ws.w[1] = Wk; ws.w[2] = Wv; ws.w[3] = Wb; ws.w[4] = Wg;
        ws.nper = 512;
        dim3 grid(NPROJ / BN, MM / BM);
        gemm_bt_kernel<<<grid, 256>>>(inputs, ws, proj, MM, NPROJ, DD, NPROJ, nullptr);
    }
    // 2) p1,p2,p3 projection: (8192 x 96)
    {
        WSet ws; ws.w[0] = Wp1; ws.w[1] = Wp2; ws.w[2] = Wp3; ws.w[3] = Wp1; ws.w[4] = Wp1;
        ws.nper = 32;
        dim3 grid(1, MM / BM);
        gemm_bt_kernel<<<grid, 256>>>(inputs, ws, pp, MM, NP, DD, NP, nullptr);
    }
    // 3) Recurrence
    recur_kernel<<<BB * HH, 256>>>(proj, pp, term, tkp, tvp, sprev, tick, attn);

    // 4) Output projection: out = attn @ Wo^T + bo  (8192 x 512)
    {
        WSet ws; ws.w[0] = Wo; ws.w[1] = Wo; ws.w[2] = Wo; ws.w[3] = Wo; ws.w[4] = Wo;
        ws.nper = 512;
        dim3 grid(DD / BN, MM / BM);
        gemm_bt_kernel<<<grid, 256>>>(attn, ws, (float*)d_out, MM, DD, DD, DD, bo);
    }
}

// round 2
// speedup vs baseline: 1.8508x; 1.8508x over previous
#include <cuda_runtime.h>
#include <math.h>
#include <stdint.h>

// Problem constants
#define TT   256
#define BB   32
#define DD   512
#define HH   8
#define HDd  64
#define ETA  4
#define RR   4
#define FEAT 256
#define MM   (TT*BB)        // 8192
#define NPROJ 2560          // 5*H*HD
#define NPP   128           // padded p-proj cols (p1,p2,p3 = 96 + 32 pad)

// Scratch (device globals; allocation-free per harness rules)
__device__ float g_x   [(size_t)MM * DD];      // tf32-rounded inputs
__device__ float g_w5  [(size_t)NPROJ * DD];   // tf32-rounded Wq|Wk|Wv|Wb|Wg
__device__ float g_wp  [(size_t)NPP * DD];     // tf32-rounded Wp1|Wp2|Wp3|zeros
__device__ float g_wo  [(size_t)DD * DD];      // tf32-rounded Wo
__device__ float g_proj[(size_t)MM * NPROJ];
__device__ float g_p   [(size_t)MM * NPP];
__device__ float g_attn[(size_t)MM * DD];      // tf32-rounded attn

__device__ __forceinline__ float tf32r(float x) {
    float r;
    asm("cvt.rna.tf32.f32 %0, %1;" : "=f"(r) : "f"(x));
    return r;
}

// Convert (round-to-tf32) kernel; src==nullptr -> write zeros
__global__ void cvt_kernel(float* __restrict__ dst, const float* __restrict__ src, int n) {
    int i = blockIdx.x * 256 + threadIdx.x;
    if (i < n) dst[i] = src ? tf32r(src[i]) : 0.0f;
}

// ---------------------------------------------------------------------------
// TF32 tensor-core GEMM: C[M x N] = A[M x K] @ B[N x K]^T (+bias)
// BM=BN=128, BK=16, 256 threads (8 warps, warp grid 2m x 4n, warp tile 64x32)
// Requires: M%128==0, N%128==0, K%16==0, row pointers 16B-aligned.
// ---------------------------------------------------------------------------
#define GBM 128
#define GBN 128
#define GBK 16
#define KPAD 20   // pad 16->20 floats: conflict-free ldmatrix phases

__global__ __launch_bounds__(256) void mma_gemm(
    const float* __restrict__ A, const float* __restrict__ B,
    float* __restrict__ C, int M, int N, int K, const float* __restrict__ bias)
{
    __shared__ float As[2][GBM * KPAD];
    __shared__ float Bs[2][GBN * KPAD];

    const int tid  = threadIdx.x;
    const int lane = tid & 31;
    const int wid  = tid >> 5;
    const int wm   = wid & 1;   // warp m index (0..1) -> 64 rows
    const int wn   = wid >> 1;  // warp n index (0..3) -> 32 cols
    const int m0   = blockIdx.y * GBM;
    const int n0   = blockIdx.x * GBN;

    const unsigned asbase = (unsigned)__cvta_generic_to_shared(&As[0][0]);
    const unsigned bsbase = (unsigned)__cvta_generic_to_shared(&Bs[0][0]);

    // ldmatrix per-lane row/col offsets
    const int a_r  = lane & 15;          // row within 16-row tile
    const int a_k4 = (lane >> 4) * 4;    // 0 or 4 (k half)
    const int b_n  = lane & 7;           // row (n) within 8-col tile
    const int b_k4 = (lane >> 3) * 4;    // 0,4,8,12 (k quarter)

    float acc[4][4][4];
#pragma unroll
    for (int i = 0; i < 4; i++)
#pragma unroll
        for (int j = 0; j < 4; j++)
#pragma unroll
            for (int c = 0; c < 4; c++) acc[i][j][c] = 0.f;

    auto prefetch = [&](int it, int buf) {
        const int k0 = it * GBK;
#pragma unroll
        for (int i = 0; i < 2; i++) {
            int idx = tid + i * 256;          // 0..511
            int r   = idx >> 2;               // 0..127
            int k4  = (idx & 3) * 4;          // 0,4,8,12
            unsigned da = asbase + (unsigned)((buf * GBM * KPAD + r * KPAD + k4) * 4);
            const float* sa = A + (size_t)(m0 + r) * K + k0 + k4;
            asm volatile("cp.async.ca.shared.global [%0], [%1], 16;\n" :: "r"(da), "l"(sa));
            unsigned db = bsbase + (unsigned)((buf * GBN * KPAD + r * KPAD + k4) * 4);
            const float* sb = B + (size_t)(n0 + r) * K + k0 + k4;
            asm volatile("cp.async.ca.shared.global [%0], [%1], 16;\n" :: "r"(db), "l"(sb));
        }
        asm volatile("cp.async.commit_group;\n");
    };

    const int NIT = K / GBK;
    prefetch(0, 0);

    for (int it = 0; it < NIT; ++it) {
        const int buf = it & 1;
        if (it + 1 < NIT) {
            prefetch(it + 1, buf ^ 1);
            asm volatile("cp.async.wait_group 1;\n");
        } else {
            asm volatile("cp.async.wait_group 0;\n");
        }
        __syncthreads();

        // B fragments: per n8 tile, one x4 ldmatrix covers k=0..15 (b0,b1 for both k8)
        uint32_t bf[4][4];
#pragma unroll
        for (int nt = 0; nt < 4; nt++) {
            unsigned addr = bsbase + (unsigned)((buf * GBN * KPAD +
                            (wn * 32 + nt * 8 + b_n) * KPAD + b_k4) * 4);
            asm volatile("ldmatrix.sync.aligned.m8n8.x4.shared.b16 {%0,%1,%2,%3}, [%4];"
                : "=r"(bf[nt][0]), "=r"(bf[nt][1]), "=r"(bf[nt][2]), "=r"(bf[nt][3])
                : "r"(addr));
        }

#pragma unroll
        for (int k8 = 0; k8 < 2; k8++) {
            uint32_t af[4][4];
#pragma unroll
            for (int mt = 0; mt < 4; mt++) {
                unsigned addr = asbase + (unsigned)((buf * GBM * KPAD +
                                (wm * 64 + mt * 16 + a_r) * KPAD + k8 * 8 + a_k4) * 4);
                asm volatile("ldmatrix.sync.aligned.m8n8.x4.shared.b16 {%0,%1,%2,%3}, [%4];"
                    : "=r"(af[mt][0]), "=r"(af[mt][1]), "=r"(af[mt][2]), "=r"(af[mt][3])
                    : "r"(addr));
            }
#pragma unroll
            for (int mt = 0; mt < 4; mt++)
#pragma unroll
                for (int nt = 0; nt < 4; nt++) {
                    asm volatile(
                        "mma.sync.aligned.m16n8k8.row.col.f32.tf32.tf32.f32 "
                        "{%0,%1,%2,%3}, {%4,%5,%6,%7}, {%8,%9}, {%0,%1,%2,%3};"
                        : "+f"(acc[mt][nt][0]), "+f"(acc[mt][nt][1]),
                          "+f"(acc[mt][nt][2]), "+f"(acc[mt][nt][3])
                        : "r"(af[mt][0]), "r"(af[mt][1]), "r"(af[mt][2]), "r"(af[mt][3]),
                          "r"(bf[nt][k8 * 2]), "r"(bf[nt][k8 * 2 + 1]));
                }
        }
        __syncthreads();
    }

    // Epilogue
#pragma unroll
    for (int mt = 0; mt < 4; mt++) {
        int row = m0 + wm * 64 + mt * 16 + (lane >> 2);
#pragma unroll
        for (int nt = 0; nt < 4; nt++) {
            int col = n0 + wn * 32 + nt * 8 + (lane & 3) * 2;
            float b0v = bias ? bias[col]     : 0.f;
            float b1v = bias ? bias[col + 1] : 0.f;
            float2 v0 = make_float2(acc[mt][nt][0] + b0v, acc[mt][nt][1] + b1v);
            float2 v1 = make_float2(acc[mt][nt][2] + b0v, acc[mt][nt][3] + b1v);
            *reinterpret_cast<float2*>(&C[(size_t)row * N + col]) = v0;
            *reinterpret_cast<float2*>(&C[(size_t)(row + 8) * N + col]) = v1;
        }
    }
}

// ---------------------------------------------------------------------------
// Recurrence kernel: one block per (b,h); 256 threads = one per FEAT element.
// ---------------------------------------------------------------------------
__device__ __forceinline__ float sigf(float x) {
    return 1.f / (1.f + __expf(-x));
}

__global__ __launch_bounds__(256) void recur_kernel(
    const float* __restrict__ proj,   // [MM][2560]
    const float* __restrict__ pproj,  // [MM][128]
    const int*   __restrict__ term,   // [MM]
    const float* __restrict__ tkp,    // (B,R,H,FEAT)
    const float* __restrict__ tvp,    // (B,R,H,HD)
    const float* __restrict__ sprev,  // (B,H,FEAT)
    const float* __restrict__ tick,   // (B,)
    float* __restrict__ attn)         // [MM][512], tf32-rounded on write
{
    const int bh = blockIdx.x;
    const int b = bh >> 3;
    const int h = bh & 7;
    const int tid = threadIdx.x;
    const int e = tid >> 6;
    const int d = tid & 63;

    __shared__ float sq[64], sk[64], sv[64], sb[64], sg[64];
    __shared__ float sp1[4], sp2[4], sp3[4];
    __shared__ float red[5][8];
    __shared__ float fin[5];
    __shared__ float kvbuf[256];

    float ks0 = tkp[((size_t)(b * RR + 0) * HH + h) * FEAT + tid];
    float ks1 = tkp[((size_t)(b * RR + 1) * HH + h) * FEAT + tid];
    float ks2 = tkp[((size_t)(b * RR + 2) * HH + h) * FEAT + tid];
    float ks3 = tkp[((size_t)(b * RR + 3) * HH + h) * FEAT + tid];
    float vs  = tvp[((size_t)(b * RR + e) * HH + h) * HDd + d];
    float ss  = sprev[((size_t)(b * HH + h)) * FEAT + tid];

    const float PI = 3.14159265358979323846f;
    const float tk = tick[b];

    float cr0, cr1, cr2, cr3, sr0, sr1, sr2, sr3;
    float cw0, cw1, cw2, cw3, sw0, sw1, sw2, sw3;
    {
        float om0 = -PI;
        float om1 = -PI + 2.f * PI / 3.f;
        float om2 = -PI + 4.f * PI / 3.f;
        float om3 = PI;
        float a;
        a = (1.f + tk) * om0; cr0 = cosf(a); sr0 = sinf(a);
        a = (1.f + tk) * om1; cr1 = cosf(a); sr1 = sinf(a);
        a = (1.f + tk) * om2; cr2 = cosf(a); sr2 = sinf(a);
        a = (1.f + tk) * om3; cr3 = cosf(a); sr3 = sinf(a);
        cw0 = cosf(om0); sw0 = sinf(om0);
        cw1 = cosf(om1); sw1 = sinf(om1);
        cw2 = cosf(om2); sw2 = sinf(om2);
        cw3 = cosf(om3); sw3 = sinf(om3);
    }

    for (int t = 0; t < TT; t++) {
        const int m = t * BB + b;
        const float* pr = proj + (size_t)m * NPROJ + h * HDd;

        if (tid < 64) {
            sq[tid] = pr[tid];
        } else if (tid < 128) {
            sk[tid - 64] = pr[512 + (tid - 64)];
            sg[tid - 64] = sigf(pr[2048 + (tid - 64)]);
        } else if (tid < 192) {
            sv[tid - 128] = pr[1024 + (tid - 128)];
        } else {
            sb[tid - 192] = sigf(pr[1536 + (tid - 192)]);
        }
        const float* pp = pproj + (size_t)m * NPP + h * ETA;
        if (tid < 4)       sp1[tid]     = pp[tid];
        else if (tid < 8)  sp2[tid - 4] = pp[32 + (tid - 4)];
        else if (tid < 12) sp3[tid - 8] = sigf(pp[64 + (tid - 8)]);

        const float tf = 1.f - (float)term[m];
        __syncthreads();

        const float qd = sq[d], kd = sk[d];
        const float phi = fmaxf(qd * sp2[e], 0.f);
        const float psi = fmaxf(kd * sp1[e], 0.f);
        const float gf  = sg[d] * sp3[e];
        const float gk  = psi * gf;
        const float dg  = (1.f - gf) * tf;

        ss = dg * ss + gk;
        float v4 = ss * phi;

        ks0 = dg * ks0 + gk * cr0;
        ks1 = dg * ks1 + gk * cr1;
        ks2 = dg * ks2 + gk * cr2;
        ks3 = dg * ks3 + gk * cr3;
        float v0 = ks0 * phi;
        float v1 = ks1 * phi;
        float v2 = ks2 * phi;
        float v3 = ks3 * phi;

        float ce = (e == 0) ? cr0 : (e == 1) ? cr1 : (e == 2) ? cr2 : cr3;
        const float bd = sb[d];
        const float vv = sv[d];
        vs = (1.f - bd) * tf * vs + (vv * bd) * ce;

#pragma unroll
        for (int o = 16; o > 0; o >>= 1) {
            v0 += __shfl_down_sync(0xffffffffu, v0, o);
            v1 += __shfl_down_sync(0xffffffffu, v1, o);
            v2 += __shfl_down_sync(0xffffffffu, v2, o);
            v3 += __shfl_down_sync(0xffffffffu, v3, o);
            v4 += __shfl_down_sync(0xffffffffu, v4, o);
        }
        const int warp = tid >> 5;
        if ((tid & 31) == 0) {
            red[0][warp] = v0;
            red[1][warp] = v1;
            red[2][warp] = v2;
            red[3][warp] = v3;
            red[4][warp] = v4;
        }
        __syncthreads();
        if (tid < 5) {
            float s = 0.f;
#pragma unroll
            for (int w = 0; w < 8; w++) s += red[tid][w];
            fin[tid] = s;
        }
        __syncthreads();

        const float kdq_e = fin[e];
        const float norm  = fin[4];
        kvbuf[tid] = vs * kdq_e;
        __syncthreads();

        if (tid < 64) {
            float kv = kvbuf[tid] + kvbuf[tid + 64] + kvbuf[tid + 128] + kvbuf[tid + 192];
            attn[(size_t)m * DD + h * HDd + tid] = tf32r(kv / (8.f * norm + 1e-6f));
        }

        float c2, s2;
        c2 = cr0 * cw0 - sr0 * sw0; s2 = sr0 * cw0 + cr0 * sw0; cr0 = c2; sr0 = s2;
        c2 = cr1 * cw1 - sr1 * sw1; s2 = sr1 * cw1 + cr1 * sw1; cr1 = c2; sr1 = s2;
        c2 = cr2 * cw2 - sr2 * sw2; s2 = sr2 * cw2 + cr2 * sw2; cr2 = c2; sr2 = s2;
        c2 = cr3 * cw3 - sr3 * sw3; s2 = sr3 * cw3 + cr3 * sw3; cr3 = c2; sr3 = s2;
    }
}

// ---------------------------------------------------------------------------
extern "C" void kernel_launch(void* const* d_in, const int* in_sizes, int n_in,
                              void* d_out, int out_size)
{
    const float* inputs = (const float*)d_in[0];
    const int*   term   = (const int*)d_in[1];
    const float* tkp    = (const float*)d_in[2];
    const float* tvp    = (const float*)d_in[3];
    const float* sprev  = (const float*)d_in[4];
    const float* tick   = (const float*)d_in[5];
    const float* Wq     = (const float*)d_in[6];
    const float* Wk     = (const float*)d_in[7];
    const float* Wv     = (const float*)d_in[8];
    const float* Wb     = (const float*)d_in[9];
    const float* Wg     = (const float*)d_in[10];
    const float* Wp1    = (const float*)d_in[11];
    const float* Wp2    = (const float*)d_in[12];
    const float* Wp3    = (const float*)d_in[13];
    const float* Wo     = (const float*)d_in[14];
    const float* bo     = (const float*)d_in[15];

    void* p;
    cudaGetSymbolAddress(&p, g_x);    float* x    = (float*)p;
    cudaGetSymbolAddress(&p, g_w5);   float* w5   = (float*)p;
    cudaGetSymbolAddress(&p, g_wp);   float* wp   = (float*)p;
    cudaGetSymbolAddress(&p, g_wo);   float* wo   = (float*)p;
    cudaGetSymbolAddress(&p, g_proj); float* proj = (float*)p;
    cudaGetSymbolAddress(&p, g_p);    float* pp   = (float*)p;
    cudaGetSymbolAddress(&p, g_attn); float* attn = (float*)p;

    const int WSZ = HH * HDd * DD;    // 262144
    const int PSZ = HH * ETA * DD;    // 16384

    // Prep: round everything the tensor cores touch to tf32 (RNA).
    cvt_kernel<<<(MM * DD + 255) / 256, 256>>>(x, inputs, MM * DD);
    cvt_kernel<<<(WSZ + 255) / 256, 256>>>(w5 + 0 * (size_t)WSZ, Wq, WSZ);
    cvt_kernel<<<(WSZ + 255) / 256, 256>>>(w5 + 1 * (size_t)WSZ, Wk, WSZ);
    cvt_kernel<<<(WSZ + 255) / 256, 256>>>(w5 + 2 * (size_t)WSZ, Wv, WSZ);
    cvt_kernel<<<(WSZ + 255) / 256, 256>>>(w5 + 3 * (size_t)WSZ, Wb, WSZ);
    cvt_kernel<<<(WSZ + 255) / 256, 256>>>(w5 + 4 * (size_t)WSZ, Wg, WSZ);
    cvt_kernel<<<(PSZ + 255) / 256, 256>>>(wp + 0 * (size_t)PSZ, Wp1, PSZ);
    cvt_kernel<<<(PSZ + 255) / 256, 256>>>(wp + 1 * (size_t)PSZ, Wp2, PSZ);
    cvt_kernel<<<(PSZ + 255) / 256, 256>>>(wp + 2 * (size_t)PSZ, Wp3, PSZ);
    cvt_kernel<<<(2 * PSZ + 255) / 256, 256>>>(wp + 3 * (size_t)PSZ, nullptr, 2 * PSZ); // pad rows 96..127
    cvt_kernel<<<(WSZ + 255) / 256, 256>>>(wo, Wo, WSZ);

    // 1) q,k,v,beta,gamma projection: (8192 x 2560)
    {
        dim3 grid(NPROJ / GBN, MM / GBM);
        mma_gemm<<<grid, 256>>>(x, w5, proj, MM, NPROJ, DD, nullptr);
    }
    // 2) p1,p2,p3 projection: (8192 x 128 padded)
    {
        dim3 grid(NPP / GBN, MM / GBM);
        mma_gemm<<<grid, 256>>>(x, wp, pp, MM, NPP, DD, nullptr);
    }
    // 3) Recurrence
    recur_kernel<<<BB * HH, 256>>>(proj, pp, term, tkp, tvp, sprev, tick, attn);

    // 4) Output projection: out = attn @ Wo^T + bo  (8192 x 512)
    {
        dim3 grid(DD / GBN, MM / GBM);
        mma_gemm<<<grid, 256>>>(attn, wo, (float*)d_out, MM, DD, DD, bo);
    }
}

// round 3
// speedup vs baseline: 2.8978x; 1.5658x over previous
#include <cuda_runtime.h>
#include <math.h>
#include <stdint.h>

// Problem constants
#define TT   256
#define BB   32
#define DD   512
#define HH   8
#define HDd  64
#define ETA  4
#define RR   4
#define FEAT 256
#define MM   (TT*BB)        // 8192
#define NPROJ 2560          // 5*H*HD
#define NPP   128           // padded p-proj cols (p1,p2,p3 = 96 + 32 pad)

// Scratch (device globals; allocation-free per harness rules)
__device__ float g_x   [(size_t)MM * DD];      // tf32-rounded inputs
__device__ float g_w5  [(size_t)NPROJ * DD];   // tf32-rounded Wq|Wk|Wv|Wb|Wg
__device__ float g_wp  [(size_t)NPP * DD];     // tf32-rounded Wp1|Wp2|Wp3|zeros
__device__ float g_wo  [(size_t)DD * DD];      // tf32-rounded Wo
__device__ float g_proj[(size_t)MM * NPROJ];
__device__ float g_p   [(size_t)MM * NPP];
__device__ float g_attn[(size_t)MM * DD];      // tf32-rounded attn

__device__ __forceinline__ float tf32r(float x) {
    float r;
    asm("cvt.rna.tf32.f32 %0, %1;" : "=f"(r) : "f"(x));
    return r;
}

// Single-source convert
__global__ void cvt1_kernel(float* __restrict__ dst, const float* __restrict__ src, int n) {
    int i = blockIdx.x * 256 + threadIdx.x;
    if (i < n) dst[i] = tf32r(src[i]);
}
// 5-segment convert (Wq|Wk|Wv|Wb|Wg)
__global__ void cvt5_kernel(float* __restrict__ dst,
                            const float* __restrict__ s0, const float* __restrict__ s1,
                            const float* __restrict__ s2, const float* __restrict__ s3,
                            const float* __restrict__ s4, int per) {
    int i = blockIdx.x * 256 + threadIdx.x;
    if (i >= 5 * per) return;
    int seg = i / per, j = i - seg * per;
    const float* s = (seg == 0) ? s0 : (seg == 1) ? s1 : (seg == 2) ? s2 : (seg == 3) ? s3 : s4;
    dst[i] = tf32r(s[j]);
}
// 3-segment + zero-pad convert (Wp1|Wp2|Wp3|0)
__global__ void cvtp_kernel(float* __restrict__ dst,
                            const float* __restrict__ s0, const float* __restrict__ s1,
                            const float* __restrict__ s2, int per) {
    int i = blockIdx.x * 256 + threadIdx.x;
    if (i >= 4 * per) return;
    int seg = i / per, j = i - seg * per;
    float v = 0.f;
    if (seg == 0) v = tf32r(s0[j]);
    else if (seg == 1) v = tf32r(s1[j]);
    else if (seg == 2) v = tf32r(s2[j]);
    dst[i] = v;
}

// ---------------------------------------------------------------------------
// TF32 tensor-core GEMM: C[M x N] = A[M x K] @ B[N x K]^T (+bias)
// ---------------------------------------------------------------------------
#define GBM 128
#define GBN 128
#define GBK 16
#define KPAD 20

__global__ __launch_bounds__(256) void mma_gemm(
    const float* __restrict__ A, const float* __restrict__ B,
    float* __restrict__ C, int M, int N, int K, const float* __restrict__ bias)
{
    __shared__ float As[2][GBM * KPAD];
    __shared__ float Bs[2][GBN * KPAD];

    const int tid  = threadIdx.x;
    const int lane = tid & 31;
    const int wid  = tid >> 5;
    const int wm   = wid & 1;
    const int wn   = wid >> 1;
    const int m0   = blockIdx.y * GBM;
    const int n0   = blockIdx.x * GBN;

    const unsigned asbase = (unsigned)__cvta_generic_to_shared(&As[0][0]);
    const unsigned bsbase = (unsigned)__cvta_generic_to_shared(&Bs[0][0]);

    const int a_r  = lane & 15;
    const int a_k4 = (lane >> 4) * 4;
    const int b_n  = lane & 7;
    const int b_k4 = (lane >> 3) * 4;

    float acc[4][4][4];
#pragma unroll
    for (int i = 0; i < 4; i++)
#pragma unroll
        for (int j = 0; j < 4; j++)
#pragma unroll
            for (int c = 0; c < 4; c++) acc[i][j][c] = 0.f;

    auto prefetch = [&](int it, int buf) {
        const int k0 = it * GBK;
#pragma unroll
        for (int i = 0; i < 2; i++) {
            int idx = tid + i * 256;
            int r   = idx >> 2;
            int k4  = (idx & 3) * 4;
            unsigned da = asbase + (unsigned)((buf * GBM * KPAD + r * KPAD + k4) * 4);
            const float* sa = A + (size_t)(m0 + r) * K + k0 + k4;
            asm volatile("cp.async.ca.shared.global [%0], [%1], 16;\n" :: "r"(da), "l"(sa));
            unsigned db = bsbase + (unsigned)((buf * GBN * KPAD + r * KPAD + k4) * 4);
            const float* sb = B + (size_t)(n0 + r) * K + k0 + k4;
            asm volatile("cp.async.ca.shared.global [%0], [%1], 16;\n" :: "r"(db), "l"(sb));
        }
        asm volatile("cp.async.commit_group;\n");
    };

    const int NIT = K / GBK;
    prefetch(0, 0);

    for (int it = 0; it < NIT; ++it) {
        const int buf = it & 1;
        if (it + 1 < NIT) {
            prefetch(it + 1, buf ^ 1);
            asm volatile("cp.async.wait_group 1;\n");
        } else {
            asm volatile("cp.async.wait_group 0;\n");
        }
        __syncthreads();

        uint32_t bf[4][4];
#pragma unroll
        for (int nt = 0; nt < 4; nt++) {
            unsigned addr = bsbase + (unsigned)((buf * GBN * KPAD +
                            (wn * 32 + nt * 8 + b_n) * KPAD + b_k4) * 4);
            asm volatile("ldmatrix.sync.aligned.m8n8.x4.shared.b16 {%0,%1,%2,%3}, [%4];"
                : "=r"(bf[nt][0]), "=r"(bf[nt][1]), "=r"(bf[nt][2]), "=r"(bf[nt][3])
                : "r"(addr));
        }

#pragma unroll
        for (int k8 = 0; k8 < 2; k8++) {
            uint32_t af[4][4];
#pragma unroll
            for (int mt = 0; mt < 4; mt++) {
                unsigned addr = asbase + (unsigned)((buf * GBM * KPAD +
                                (wm * 64 + mt * 16 + a_r) * KPAD + k8 * 8 + a_k4) * 4);
                asm volatile("ldmatrix.sync.aligned.m8n8.x4.shared.b16 {%0,%1,%2,%3}, [%4];"
                    : "=r"(af[mt][0]), "=r"(af[mt][1]), "=r"(af[mt][2]), "=r"(af[mt][3])
                    : "r"(addr));
            }
#pragma unroll
            for (int mt = 0; mt < 4; mt++)
#pragma unroll
                for (int nt = 0; nt < 4; nt++) {
                    asm volatile(
                        "mma.sync.aligned.m16n8k8.row.col.f32.tf32.tf32.f32 "
                        "{%0,%1,%2,%3}, {%4,%5,%6,%7}, {%8,%9}, {%0,%1,%2,%3};"
                        : "+f"(acc[mt][nt][0]), "+f"(acc[mt][nt][1]),
                          "+f"(acc[mt][nt][2]), "+f"(acc[mt][nt][3])
                        : "r"(af[mt][0]), "r"(af[mt][1]), "r"(af[mt][2]), "r"(af[mt][3]),
                          "r"(bf[nt][k8 * 2]), "r"(bf[nt][k8 * 2 + 1]));
                }
        }
        __syncthreads();
    }

#pragma unroll
    for (int mt = 0; mt < 4; mt++) {
        int row = m0 + wm * 64 + mt * 16 + (lane >> 2);
#pragma unroll
        for (int nt = 0; nt < 4; nt++) {
            int col = n0 + wn * 32 + nt * 8 + (lane & 3) * 2;
            float b0v = bias ? bias[col]     : 0.f;
            float b1v = bias ? bias[col + 1] : 0.f;
            float2 v0 = make_float2(acc[mt][nt][0] + b0v, acc[mt][nt][1] + b1v);
            float2 v1 = make_float2(acc[mt][nt][2] + b0v, acc[mt][nt][3] + b1v);
            *reinterpret_cast<float2*>(&C[(size_t)row * N + col]) = v0;
            *reinterpret_cast<float2*>(&C[(size_t)(row + 8) * N + col]) = v1;
        }
    }
}

// ---------------------------------------------------------------------------
// Recurrence kernel v2: cp.async double-buffered operand staging, 3 barriers.
// One block per (b,h); 256 threads = one per FEAT element (e = tid>>6, d = tid&63).
// ---------------------------------------------------------------------------
__device__ __forceinline__ float sigf(float x) {
    return 1.f / (1.f + __expf(-x));
}

__global__ __launch_bounds__(256) void recur_kernel(
    const float* __restrict__ proj,   // [MM][2560] raw q|k|v|b|g
    const float* __restrict__ pproj,  // [MM][128] raw p1|p2|p3|pad
    const int*   __restrict__ term,   // [MM]
    const float* __restrict__ tkp,    // (B,R,H,FEAT)
    const float* __restrict__ tvp,    // (B,R,H,HD)
    const float* __restrict__ sprev,  // (B,H,FEAT)
    const float* __restrict__ tick,   // (B,)
    float* __restrict__ attn)         // [MM][512], tf32-rounded on write
{
    const int bh = blockIdx.x;
    const int b = bh >> 3;
    const int h = bh & 7;
    const int tid = threadIdx.x;
    const int e = tid >> 6;
    const int d = tid & 63;

    __shared__ __align__(16) float sstage[2][5][64];  // q,k,v,b_raw,g_raw
    __shared__ __align__(16) float sp[2][3][4];       // p1,p2,p3_raw
    __shared__ int sterm[2];
    __shared__ float red[5][8];
    __shared__ float kvbuf[256];

    // Initial states
    float ks0 = tkp[((size_t)(b * RR + 0) * HH + h) * FEAT + tid];
    float ks1 = tkp[((size_t)(b * RR + 1) * HH + h) * FEAT + tid];
    float ks2 = tkp[((size_t)(b * RR + 2) * HH + h) * FEAT + tid];
    float ks3 = tkp[((size_t)(b * RR + 3) * HH + h) * FEAT + tid];
    float vs  = tvp[((size_t)(b * RR + e) * HH + h) * HDd + d];
    float ss  = sprev[((size_t)(b * HH + h)) * FEAT + tid];

    const float PI = 3.14159265358979323846f;
    const float tk = tick[b];

    float cr0, cr1, cr2, cr3, sr0, sr1, sr2, sr3;
    float cw0, cw1, cw2, cw3, sw0, sw1, sw2, sw3;
    {
        float om0 = -PI;
        float om1 = -PI + 2.f * PI / 3.f;
        float om2 = -PI + 4.f * PI / 3.f;
        float om3 = PI;
        float a;
        a = (1.f + tk) * om0; cr0 = cosf(a); sr0 = sinf(a);
        a = (1.f + tk) * om1; cr1 = cosf(a); sr1 = sinf(a);
        a = (1.f + tk) * om2; cr2 = cosf(a); sr2 = sinf(a);
        a = (1.f + tk) * om3; cr3 = cosf(a); sr3 = sinf(a);
        cw0 = cosf(om0); sw0 = sinf(om0);
        cw1 = cosf(om1); sw1 = sinf(om1);
        cw2 = cosf(om2); sw2 = sinf(om2);
        cw3 = cosf(om3); sw3 = sinf(om3);
    }

    // Async stage of step t's operands into buffer `buf`
    auto stage = [&](int t, int buf) {
        const int m = t * BB + b;
        if (tid < 80) {
            const int seg = tid >> 4;
            const int j = (tid & 15) * 4;
            const float* src = proj + (size_t)m * NPROJ + seg * 512 + h * HDd + j;
            unsigned dst = (unsigned)__cvta_generic_to_shared(&sstage[buf][seg][j]);
            asm volatile("cp.async.ca.shared.global [%0], [%1], 16;\n" :: "r"(dst), "l"(src));
        } else if (tid < 83) {
            const int j = tid - 80;
            const float* src = pproj + (size_t)m * NPP + j * 32 + h * ETA;
            unsigned dst = (unsigned)__cvta_generic_to_shared(&sp[buf][j][0]);
            asm volatile("cp.async.ca.shared.global [%0], [%1], 16;\n" :: "r"(dst), "l"(src));
        } else if (tid == 83) {
            const int* src = term + m;
            unsigned dst = (unsigned)__cvta_generic_to_shared(&sterm[buf]);
            asm volatile("cp.async.ca.shared.global [%0], [%1], 4;\n" :: "r"(dst), "l"(src));
        }
        asm volatile("cp.async.commit_group;\n");
    };

    stage(0, 0);

    for (int t = 0; t < TT; t++) {
        const int buf = t & 1;
        if (t + 1 < TT) {
            stage(t + 1, buf ^ 1);
            asm volatile("cp.async.wait_group 1;\n");
        } else {
            asm volatile("cp.async.wait_group 0;\n");
        }
        __syncthreads();   // S1: stage buf visible to all

        const float qd = sstage[buf][0][d];
        const float kd = sstage[buf][1][d];
        const float vv = sstage[buf][2][d];
        const float bd = sigf(sstage[buf][3][d]);
        const float gd = sigf(sstage[buf][4][d]);
        const float p1e = sp[buf][0][e];
        const float p2e = sp[buf][1][e];
        const float p3e = sigf(sp[buf][2][e]);
        const float tf = 1.f - (float)sterm[buf];

        const float phi = fmaxf(qd * p2e, 0.f);
        const float psi = fmaxf(kd * p1e, 0.f);
        const float gf  = gd * p3e;
        const float gk  = psi * gf;
        const float dg  = (1.f - gf) * tf;

        ss = dg * ss + gk;
        float v4 = ss * phi;

        ks0 = dg * ks0 + gk * cr0;
        ks1 = dg * ks1 + gk * cr1;
        ks2 = dg * ks2 + gk * cr2;
        ks3 = dg * ks3 + gk * cr3;
        float v0 = ks0 * phi;
        float v1 = ks1 * phi;
        float v2 = ks2 * phi;
        float v3 = ks3 * phi;

        const float ce = (e == 0) ? cr0 : (e == 1) ? cr1 : (e == 2) ? cr2 : cr3;
        vs = (1.f - bd) * tf * vs + (vv * bd) * ce;

#pragma unroll
        for (int o = 16; o > 0; o >>= 1) {
            v0 += __shfl_down_sync(0xffffffffu, v0, o);
            v1 += __shfl_down_sync(0xffffffffu, v1, o);
            v2 += __shfl_down_sync(0xffffffffu, v2, o);
            v3 += __shfl_down_sync(0xffffffffu, v3, o);
            v4 += __shfl_down_sync(0xffffffffu, v4, o);
        }
        const int warp = tid >> 5;
        if ((tid & 31) == 0) {
            red[0][warp] = v0;
            red[1][warp] = v1;
            red[2][warp] = v2;
            red[3][warp] = v3;
            red[4][warp] = v4;
        }
        __syncthreads();   // S2: per-warp partials visible

        // Every thread sums the 8 partials it needs (no extra barrier)
        float kdq_e = 0.f, norm = 0.f;
#pragma unroll
        for (int w = 0; w < 8; w++) {
            kdq_e += red[e][w];
            norm  += red[4][w];
        }

        kvbuf[tid] = vs * kdq_e;
        __syncthreads();   // S3: kvbuf visible

        if (tid < 64) {
            const int m = t * BB + b;
            float kv = kvbuf[tid] + kvbuf[tid + 64] + kvbuf[tid + 128] + kvbuf[tid + 192];
            attn[(size_t)m * DD + h * HDd + tid] = tf32r(kv / (8.f * norm + 1e-6f));
        }

        float c2, s2;
        c2 = cr0 * cw0 - sr0 * sw0; s2 = sr0 * cw0 + cr0 * sw0; cr0 = c2; sr0 = s2;
        c2 = cr1 * cw1 - sr1 * sw1; s2 = sr1 * cw1 + cr1 * sw1; cr1 = c2; sr1 = s2;
        c2 = cr2 * cw2 - sr2 * sw2; s2 = sr2 * cw2 + cr2 * sw2; cr2 = c2; sr2 = s2;
        c2 = cr3 * cw3 - sr3 * sw3; s2 = sr3 * cw3 + cr3 * sw3; cr3 = c2; sr3 = s2;
    }
}

// ---------------------------------------------------------------------------
extern "C" void kernel_launch(void* const* d_in, const int* in_sizes, int n_in,
                              void* d_out, int out_size)
{
    const float* inputs = (const float*)d_in[0];
    const int*   term   = (const int*)d_in[1];
    const float* tkp    = (const float*)d_in[2];
    const float* tvp    = (const float*)d_in[3];
    const float* sprev  = (const float*)d_in[4];
    const float* tick   = (const float*)d_in[5];
    const float* Wq     = (const float*)d_in[6];
    const float* Wk     = (const float*)d_in[7];
    const float* Wv     = (const float*)d_in[8];
    const float* Wb     = (const float*)d_in[9];
    const float* Wg     = (const float*)d_in[10];
    const float* Wp1    = (const float*)d_in[11];
    const float* Wp2    = (const float*)d_in[12];
    const float* Wp3    = (const float*)d_in[13];
    const float* Wo     = (const float*)d_in[14];
    const float* bo     = (const float*)d_in[15];

    void* p;
    cudaGetSymbolAddress(&p, g_x);    float* x    = (float*)p;
    cudaGetSymbolAddress(&p, g_w5);   float* w5   = (float*)p;
    cudaGetSymbolAddress(&p, g_wp);   float* wp   = (float*)p;
    cudaGetSymbolAddress(&p, g_wo);   float* wo   = (float*)p;
    cudaGetSymbolAddress(&p, g_proj); float* proj = (float*)p;
    cudaGetSymbolAddress(&p, g_p);    float* pp   = (float*)p;
    cudaGetSymbolAddress(&p, g_attn); float* attn = (float*)p;

    const int WSZ = HH * HDd * DD;    // 262144
    const int PSZ = HH * ETA * DD;    // 16384

    cvt1_kernel<<<(MM * DD + 255) / 256, 256>>>(x, inputs, MM * DD);
    cvt5_kernel<<<(5 * WSZ + 255) / 256, 256>>>(w5, Wq, Wk, Wv, Wb, Wg, WSZ);
    cvtp_kernel<<<(4 * PSZ + 255) / 256, 256>>>(wp, Wp1, Wp2, Wp3, PSZ);
    cvt1_kernel<<<(WSZ + 255) / 256, 256>>>(wo, Wo, WSZ);

    // 1) q,k,v,beta,gamma projection: (8192 x 2560)
    {
        dim3 grid(NPROJ / GBN, MM / GBM);
        mma_gemm<<<grid, 256>>>(x, w5, proj, MM, NPROJ, DD, nullptr);
    }
    // 2) p1,p2,p3 projection: (8192 x 128 padded)
    {
        dim3 grid(NPP / GBN, MM / GBM);
        mma_gemm<<<grid, 256>>>(x, wp, pp, MM, NPP, DD, nullptr);
    }
    // 3) Recurrence
    recur_kernel<<<BB * HH, 256>>>(proj, pp, term, tkp, tvp, sprev, tick, attn);

    // 4) Output projection: out = attn @ Wo^T + bo  (8192 x 512)
    {
        dim3 grid(DD / GBN, MM / GBM);
        mma_gemm<<<grid, 256>>>(attn, wo, (float*)d_out, MM, DD, DD, bo);
    }
}